// round 5
// baseline (speedup 1.0000x reference)
#include <cuda_runtime.h>

#define BB 4
#define DD 4
#define HH 768
#define WW 768
#define RR 4
#define HWSZ (HH * WW)              // 589824
#define NVOX (BB * DD * HH * WW)    // 9437184

__device__ unsigned g_count;
__device__ unsigned g_list[NVOX];

__global__ void zero_kernel() { g_count = 0; }

// Load one padded row segment of 6 values: [w0-1, w0..w0+3, w0+4].
// Halo via warp shuffle; lanes 0/31 use predicated scalar loads.
__device__ __forceinline__ void load_row6(const float* __restrict__ row, int w0, int lane,
                                          float v[6]) {
    float4 c4 = *reinterpret_cast<const float4*>(row + w0);
    float lv = __shfl_up_sync(0xffffffffu, c4.w, 1);
    float rv = __shfl_down_sync(0xffffffffu, c4.x, 1);
    if (lane == 0) {
        const int wl = (w0 == 0) ? 0 : (w0 - 1);
        lv = __ldg(row + wl);
    }
    if (lane == 31) {
        const int wr = (w0 + 4 >= WW) ? (WW - 1) : (w0 + 4);
        rv = __ldg(row + wr);
    }
    v[0] = lv; v[1] = c4.x; v[2] = c4.y; v[3] = c4.z; v[4] = c4.w; v[5] = rv;
}

// Phase 1: NMS scan + trivial outputs + compaction of maxima indices.
// Block = 192 threads = one full W row; RR rows per block, sliding window.
__global__ __launch_bounds__(192)
void scan_kernel(const float* __restrict__ x, float* __restrict__ out) {
    const int tid  = threadIdx.x;
    const int lane = tid & 31;
    const int wid  = tid >> 5;
    const int w0   = tid * 4;
    const int hb   = (blockIdx.x % (HH / RR)) * RR;
    const int p    = blockIdx.x / (HH / RR);
    const int d    = p % DD;
    const int b    = p / DD;

    const int dm = (d == 0) ? 0 : d - 1;
    const int dp = (d == DD - 1) ? (DD - 1) : d + 1;
    const float* pl0 = x + ((size_t)(b * DD + dm) * HH) * WW;
    const float* pl1 = x + ((size_t)(b * DD + d ) * HH) * WW;
    const float* pl2 = x + ((size_t)(b * DD + dp) * HH) * WW;

    // v1[slot][k]  = center-plane row values
    // m02[slot][k] = max of planes d-1, d+1
    // rm9[slot][k] = max over all 3 planes
    float v1[3][6], m02[3][6], rm9[3][6];

    {
        const int ht = (hb == 0) ? 0 : (hb - 1);
        float t0[6], t1[6], t2[6];
        load_row6(pl0 + (size_t)ht * WW, w0, lane, t0);
        load_row6(pl1 + (size_t)ht * WW, w0, lane, t1);
        load_row6(pl2 + (size_t)ht * WW, w0, lane, t2);
        #pragma unroll
        for (int k = 0; k < 6; k++) {
            v1[0][k] = t1[k]; m02[0][k] = fmaxf(t0[k], t2[k]);
            rm9[0][k] = fmaxf(m02[0][k], t1[k]);
        }
        load_row6(pl0 + (size_t)hb * WW, w0, lane, t0);
        load_row6(pl1 + (size_t)hb * WW, w0, lane, t1);
        load_row6(pl2 + (size_t)hb * WW, w0, lane, t2);
        #pragma unroll
        for (int k = 0; k < 6; k++) {
            v1[1][k] = t1[k]; m02[1][k] = fmaxf(t0[k], t2[k]);
            rm9[1][k] = fmaxf(m02[1][k], t1[k]);
        }
    }

    const size_t sp = (size_t)hb * WW + w0;
    float* o0 = out + ((size_t)(b * 3 + 0) * DD + d) * HWSZ + sp;
    float* o1 = out + ((size_t)(b * 3 + 1) * DD + d) * HWSZ + sp;
    float* o2 = out + ((size_t)(b * 3 + 2) * DD + d) * HWSZ + sp;
    float* oy = out + (size_t)3 * NVOX + ((size_t)(b * DD + d)) * HWSZ + sp;

    const float fd = (float)d;
    const float4 c0q = make_float4(fd, fd, fd, fd);
    const float4 c1q = make_float4((float)w0, (float)(w0 + 1), (float)(w0 + 2), (float)(w0 + 3));

    unsigned masks[RR][4];

    #pragma unroll
    for (int r = 0; r < RR; r++) {
        const int st = r % 3;
        const int sm = (r + 1) % 3;
        const int sb = (r + 2) % 3;
        const int h  = hb + r;

        {
            const int hn = (h + 1 >= HH) ? (HH - 1) : (h + 1);
            float t0[6], t1[6], t2[6];
            load_row6(pl0 + (size_t)hn * WW, w0, lane, t0);
            load_row6(pl1 + (size_t)hn * WW, w0, lane, t1);
            load_row6(pl2 + (size_t)hn * WW, w0, lane, t2);
            #pragma unroll
            for (int k = 0; k < 6; k++) {
                v1[sb][k] = t1[k]; m02[sb][k] = fmaxf(t0[k], t2[k]);
                rm9[sb][k] = fmaxf(m02[sb][k], t1[k]);
            }
        }

        float x0q[4];
        #pragma unroll
        for (int j = 0; j < 4; j++) {
            const int c = j + 1;
            const float x0 = v1[sm][c];
            float nb = fmaxf(rm9[st][c - 1], rm9[st][c]);
            nb = fmaxf(nb, rm9[st][c + 1]);
            nb = fmaxf(nb, rm9[sb][c - 1]);
            nb = fmaxf(nb, rm9[sb][c]);
            nb = fmaxf(nb, rm9[sb][c + 1]);
            nb = fmaxf(nb, rm9[sm][c - 1]);
            nb = fmaxf(nb, rm9[sm][c + 1]);
            nb = fmaxf(nb, m02[sm][c]);
            nb = fmaxf(nb, 0.0f);
            const bool nms = (x0 > nb);
            masks[r][j] = __ballot_sync(0xffffffffu, nms);
            x0q[j] = x0;
        }

        const float fh = (float)h;
        *reinterpret_cast<float4*>(o0 + (size_t)r * WW) = c0q;
        *reinterpret_cast<float4*>(o1 + (size_t)r * WW) = c1q;
        *reinterpret_cast<float4*>(o2 + (size_t)r * WW) = make_float4(fh, fh, fh, fh);
        *reinterpret_cast<float4*>(oy + (size_t)r * WW) = make_float4(x0q[0], x0q[1], x0q[2], x0q[3]);
    }

    // ---- block-aggregated compaction ----
    __shared__ unsigned s_wtot[6];
    __shared__ unsigned s_base;

    unsigned tot = 0;
    #pragma unroll
    for (int r = 0; r < RR; r++)
        #pragma unroll
        for (int j = 0; j < 4; j++)
            tot += __popc(masks[r][j]);

    if (lane == 0) s_wtot[wid] = tot;
    __syncthreads();
    if (tid == 0) {
        unsigned t = 0;
        #pragma unroll
        for (int w2 = 0; w2 < 6; w2++) t += s_wtot[w2];
        s_base = t ? atomicAdd(&g_count, t) : 0u;
    }
    __syncthreads();

    unsigned base = s_base;
    for (int w2 = 0; w2 < wid; w2++) base += s_wtot[w2];

    const unsigned ltmask = (1u << lane) - 1u;
    const unsigned plane_idx = (unsigned)(b * DD + d) * HWSZ;

    #pragma unroll
    for (int r = 0; r < RR; r++) {
        #pragma unroll
        for (int j = 0; j < 4; j++) {
            const unsigned m = masks[r][j];
            if (m) {
                if (m & (1u << lane))
                    g_list[base + __popc(m & ltmask)] =
                        plane_idx + (unsigned)(hb + r) * WW + (unsigned)(w0 + j);
                base += __popc(m);
            }
        }
    }
}

// Phase 2: full quadratic solve at listed maxima (all interior, no clamping).
__global__ __launch_bounds__(128)
void solve_kernel(const float* __restrict__ x, float* __restrict__ out) {
    const unsigned n = g_count;
    for (unsigned i = blockIdx.x * blockDim.x + threadIdx.x; i < n;
         i += gridDim.x * blockDim.x) {
        const unsigned idx = g_list[i];
        const unsigned w  = idx % WW;
        const unsigned hp = idx / WW;
        const unsigned h  = hp % HH;
        const unsigned pd = hp / HH;
        const unsigned d  = pd % DD;
        const unsigned b  = pd / DD;

        const float* pc = x + idx;
        const float x0  = __ldg(pc);
        const float xl  = __ldg(pc - 1),        xr  = __ldg(pc + 1);
        const float yl  = __ldg(pc - WW),       yr  = __ldg(pc + WW);
        const float sl  = __ldg(pc - HWSZ),     sr  = __ldg(pc + HWSZ);
        const float ayl_l = __ldg(pc - WW - 1),   ayl_r = __ldg(pc - WW + 1);
        const float ayr_l = __ldg(pc + WW - 1),   ayr_r = __ldg(pc + WW + 1);
        const float asl_l = __ldg(pc - HWSZ - 1), asl_r = __ldg(pc - HWSZ + 1);
        const float asr_l = __ldg(pc + HWSZ - 1), asr_r = __ldg(pc + HWSZ + 1);
        const float asl_d = __ldg(pc - HWSZ - WW), asl_u = __ldg(pc - HWSZ + WW);
        const float asr_d = __ldg(pc + HWSZ - WW), asr_u = __ldg(pc + HWSZ + WW);

        const float gx = 0.5f * (xr - xl);
        const float gy = 0.5f * (yr - yl);
        const float gs = 0.5f * (sr - sl);

        const float dxx = xr - 2.0f * x0 + xl;
        const float dyy = yr - 2.0f * x0 + yl;
        const float dss = sr - 2.0f * x0 + sl;

        const float dxy =  0.25f * (ayr_r - ayr_l - ayl_r + ayl_l);
        const float dys = -0.25f * (asr_u - asr_d - asl_u + asl_d);
        const float dxs = -0.25f * (asr_r - asr_l - asl_r + asl_l);

        const float cf00 = dyy * dss - dys * dys;
        const float cf01 = dxy * dss - dys * dxs;
        const float cf02 = dxy * dys - dyy * dxs;
        const float det  = dxx * cf00 - dxy * cf01 + dxs * cf02;
        const bool solved = (det != 0.0f);
        const float sdet = solved ? det : 1.0f;
        float inv;
        asm("rcp.approx.f32 %0, %1;" : "=f"(inv) : "f"(sdet));

        const float t0 = gy * dss - dys * gs;
        const float t1 = gy * dys - dyy * gs;
        const float t2 = dxy * gs - gy * dxs;

        const float sx = (gx  * cf00 - dxy * t0   + dxs * t1) * inv;
        const float sy = (dxx * t0   - gx  * cf01 + dxs * t2) * inv;
        const float ss = (-dxx * t1  - dxy * t2   + gx  * cf02) * inv;

        // nms is true by membership in the list; valid = solved
        const float amax = fmaxf(fmaxf(fabsf(sx), fabsf(sy)), fabsf(ss));
        const bool keep = solved && (amax <= 0.7f);

        const float dx_x = keep ? -sx : 0.0f;
        const float dx_y = keep ? -sy : 0.0f;
        const float dx_s = keep ? -ss : 0.0f;

        float ym = solved ? (x0 + 10.0f) : x0;
        if (keep) {
            const float t = fmaf(gx, sx, fmaf(gy, sy, gs * ss));
            ym = fmaf(-0.5f, t, ym);
        }

        const unsigned cstride = (unsigned)DD * HWSZ;
        out[idx + (size_t)(2 * b + 0) * cstride] = (float)d + dx_s;
        out[idx + (size_t)(2 * b + 1) * cstride] = (float)w + dx_x;
        out[idx + (size_t)(2 * b + 2) * cstride] = (float)h + dx_y;
        out[(size_t)3 * NVOX + idx] = ym;
    }
}

extern "C" void kernel_launch(void* const* d_in, const int* in_sizes, int n_in,
                              void* d_out, int out_size) {
    const float* x = (const float*)d_in[0];
    float* out = (float*)d_out;
    zero_kernel<<<1, 1>>>();
    scan_kernel<<<BB * DD * (HH / RR), 192>>>(x, out);
    solve_kernel<<<1184, 128>>>(x, out);
}

// round 6
// speedup vs baseline: 1.0684x; 1.0684x over previous
#include <cuda_runtime.h>

#define BB 4
#define DD 4
#define HH 768
#define WW 768
#define RR 4

typedef unsigned long long u64;

// ---- packed f32x2 helpers (sm_100a) ----
__device__ __forceinline__ u64 f2pk(float a, float b) {
    u64 r; asm("mov.b64 %0,{%1,%2};" : "=l"(r) : "f"(a), "f"(b)); return r;
}
#define F2UNPK(lo, hi, a) asm("mov.b64 {%0,%1},%2;" : "=f"(lo), "=f"(hi) : "l"(a))
__device__ __forceinline__ u64 f2add(u64 a, u64 b) {
    u64 r; asm("add.rn.f32x2 %0,%1,%2;" : "=l"(r) : "l"(a), "l"(b)); return r;
}
__device__ __forceinline__ u64 f2mul(u64 a, u64 b) {
    u64 r; asm("mul.rn.f32x2 %0,%1,%2;" : "=l"(r) : "l"(a), "l"(b)); return r;
}
__device__ __forceinline__ u64 f2fma(u64 a, u64 b, u64 c) {
    u64 r; asm("fma.rn.f32x2 %0,%1,%2,%3;" : "=l"(r) : "l"(a), "l"(b), "l"(c)); return r;
}
#define F2_CM1  0xBF800000BF800000ULL   // (-1, -1)
#define F2_CM2  0xC0000000C0000000ULL   // (-2, -2)
#define F2_C05  0x3F0000003F000000ULL   // (0.5, 0.5)
#define F2_C025 0x3E8000003E800000ULL   // (0.25, 0.25)
// a - b, bit-exact via fma(b, -1, a)
__device__ __forceinline__ u64 f2sub(u64 a, u64 b) { return f2fma(b, F2_CM1, a); }

// Load one padded row segment of 6 values: [w0-1, w0..w0+3, w0+4].
__device__ __forceinline__ void load_row6(const float* __restrict__ row, int w0, int lane,
                                          float v[6]) {
    float4 c4 = *reinterpret_cast<const float4*>(row + w0);
    float lv = __shfl_up_sync(0xffffffffu, c4.w, 1);
    float rv = __shfl_down_sync(0xffffffffu, c4.x, 1);
    if (lane == 0) {
        const int wl = (w0 == 0) ? 0 : (w0 - 1);
        lv = __ldg(row + wl);
    }
    if (lane == 31) {
        const int wr = (w0 + 4 >= WW) ? (WW - 1) : (w0 + 4);
        rv = __ldg(row + wr);
    }
    v[0] = lv; v[1] = c4.x; v[2] = c4.y; v[3] = c4.z; v[4] = c4.w; v[5] = rv;
}

__global__ __launch_bounds__(192, 4)
void cqi3d_kernel(const float* __restrict__ x, float* __restrict__ out) {
    const int tid  = threadIdx.x;
    const int lane = tid & 31;
    const int w0   = tid * 4;
    const int hb   = (blockIdx.x % (HH / RR)) * RR;
    const int p    = blockIdx.x / (HH / RR);
    const int d    = p % DD;
    const int b    = p / DD;

    const int dm = (d == 0) ? 0 : d - 1;
    const int dp = (d == DD - 1) ? (DD - 1) : d + 1;
    const float* pl0 = x + ((size_t)(b * DD + dm) * HH) * WW;
    const float* pl1 = x + ((size_t)(b * DD + d ) * HH) * WW;
    const float* pl2 = x + ((size_t)(b * DD + dp) * HH) * WW;

    float v[3][3][6];
    float rm9[3][6];

    {
        const int ht = (hb == 0) ? 0 : (hb - 1);
        load_row6(pl0 + (size_t)ht * WW, w0, lane, v[0][0]);
        load_row6(pl1 + (size_t)ht * WW, w0, lane, v[1][0]);
        load_row6(pl2 + (size_t)ht * WW, w0, lane, v[2][0]);
        load_row6(pl0 + (size_t)hb * WW, w0, lane, v[0][1]);
        load_row6(pl1 + (size_t)hb * WW, w0, lane, v[1][1]);
        load_row6(pl2 + (size_t)hb * WW, w0, lane, v[2][1]);
        #pragma unroll
        for (int k = 0; k < 6; k++) {
            rm9[0][k] = fmaxf(fmaxf(v[0][0][k], v[1][0][k]), v[2][0][k]);
            rm9[1][k] = fmaxf(fmaxf(v[0][1][k], v[1][1][k]), v[2][1][k]);
        }
    }

    const size_t HW = (size_t)HH * WW;
    const size_t sp = (size_t)hb * WW + w0;
    float* o0 = out + ((size_t)(b * 3 + 0) * DD + d) * HW + sp;
    float* o1 = out + ((size_t)(b * 3 + 1) * DD + d) * HW + sp;
    float* o2 = out + ((size_t)(b * 3 + 2) * DD + d) * HW + sp;
    float* oy = out + (size_t)3 * BB * DD * HW + ((size_t)(b * DD + d)) * HW + sp;

    #pragma unroll
    for (int r = 0; r < RR; r++) {
        const int st = r % 3;
        const int sm = (r + 1) % 3;
        const int sb = (r + 2) % 3;
        const int h  = hb + r;

        {
            const int hn = (h + 1 >= HH) ? (HH - 1) : (h + 1);
            load_row6(pl0 + (size_t)hn * WW, w0, lane, v[0][sb]);
            load_row6(pl1 + (size_t)hn * WW, w0, lane, v[1][sb]);
            load_row6(pl2 + (size_t)hn * WW, w0, lane, v[2][sb]);
            #pragma unroll
            for (int k = 0; k < 6; k++)
                rm9[sb][k] = fmaxf(fmaxf(v[0][sb][k], v[1][sb][k]), v[2][sb][k]);
        }

        // ---- NMS for all 4 voxels (scalar) ----
        bool nmsq[4];
        #pragma unroll
        for (int j = 0; j < 4; j++) {
            const int c = j + 1;
            float nb = fmaxf(rm9[st][c - 1], rm9[st][c]);
            nb = fmaxf(nb, rm9[st][c + 1]);
            nb = fmaxf(nb, rm9[sb][c - 1]);
            nb = fmaxf(nb, rm9[sb][c]);
            nb = fmaxf(nb, rm9[sb][c + 1]);
            nb = fmaxf(nb, rm9[sm][c - 1]);
            nb = fmaxf(nb, rm9[sm][c + 1]);
            nb = fmaxf(nb, fmaxf(v[0][sm][c], v[2][sm][c]));
            nb = fmaxf(nb, 0.0f);
            nmsq[j] = (v[1][sm][c] > nb);
        }

        float oc0[4], oc1[4], oc2[4], oyv[4];

        // ---- packed solve: two voxel pairs ----
        #pragma unroll
        for (int jp = 0; jp < 2; jp++) {
            const int c0 = 1 + jp * 2;

            u64 X0 = f2pk(v[1][sm][c0],     v[1][sm][c0 + 1]);
            u64 XL = f2pk(v[1][sm][c0 - 1], v[1][sm][c0]);
            u64 XR = f2pk(v[1][sm][c0 + 1], v[1][sm][c0 + 2]);
            u64 YL = f2pk(v[1][st][c0],     v[1][st][c0 + 1]);
            u64 YR = f2pk(v[1][sb][c0],     v[1][sb][c0 + 1]);
            u64 SL = f2pk(v[0][sm][c0],     v[0][sm][c0 + 1]);
            u64 SR = f2pk(v[2][sm][c0],     v[2][sm][c0 + 1]);

            u64 GX = f2mul(f2sub(XR, XL), F2_C05);
            u64 GY = f2mul(f2sub(YR, YL), F2_C05);
            u64 GS = f2mul(f2sub(SR, SL), F2_C05);

            u64 DXX = f2add(f2fma(X0, F2_CM2, XR), XL);
            u64 DYY = f2add(f2fma(X0, F2_CM2, YR), YL);
            u64 DSS = f2add(f2fma(X0, F2_CM2, SR), SL);

            u64 DXY, DYS, DXS;
            {
                u64 br = f2pk(v[1][sb][c0 + 1], v[1][sb][c0 + 2]);
                u64 bl = f2pk(v[1][sb][c0 - 1], v[1][sb][c0]);
                u64 tr = f2pk(v[1][st][c0 + 1], v[1][st][c0 + 2]);
                u64 tl = f2pk(v[1][st][c0 - 1], v[1][st][c0]);
                DXY = f2mul(f2add(f2sub(br, bl), f2sub(tl, tr)), F2_C025);
            }
            {
                u64 p2b = f2pk(v[2][sb][c0], v[2][sb][c0 + 1]);
                u64 p2t = f2pk(v[2][st][c0], v[2][st][c0 + 1]);
                u64 p0b = f2pk(v[0][sb][c0], v[0][sb][c0 + 1]);
                u64 p0t = f2pk(v[0][st][c0], v[0][st][c0 + 1]);
                DYS = f2mul(f2add(f2sub(p2t, p2b), f2sub(p0b, p0t)), F2_C025);
            }
            {
                u64 srp = f2pk(v[2][sm][c0 + 1], v[2][sm][c0 + 2]);
                u64 srm = f2pk(v[2][sm][c0 - 1], v[2][sm][c0]);
                u64 slp = f2pk(v[0][sm][c0 + 1], v[0][sm][c0 + 2]);
                u64 slm = f2pk(v[0][sm][c0 - 1], v[0][sm][c0]);
                DXS = f2mul(f2add(f2sub(srm, srp), f2sub(slp, slm)), F2_C025);
            }

            u64 CF00 = f2sub(f2mul(DYY, DSS), f2mul(DYS, DYS));
            u64 CF01 = f2sub(f2mul(DXY, DSS), f2mul(DYS, DXS));
            u64 CF02 = f2sub(f2mul(DXY, DYS), f2mul(DYY, DXS));
            u64 DET  = f2sub(f2fma(DXS, CF02, f2mul(DXX, CF00)), f2mul(DXY, CF01));

            u64 T0 = f2sub(f2mul(GY, DSS), f2mul(DYS, GS));
            u64 T1 = f2sub(f2mul(GY, DYS), f2mul(DYY, GS));
            u64 T2 = f2sub(f2mul(DXY, GS), f2mul(GY, DXS));

            u64 NX = f2sub(f2fma(DXS, T1, f2mul(GX, CF00)), f2mul(DXY, T0));
            u64 NY = f2sub(f2fma(DXS, T2, f2mul(DXX, T0)), f2mul(GX, CF01));
            u64 NZ = f2sub(f2mul(GX, CF02), f2fma(DXY, T2, f2mul(DXX, T1)));

            float det0, det1;
            F2UNPK(det0, det1, DET);
            const bool so0 = (det0 != 0.0f);
            const bool so1 = (det1 != 0.0f);
            float i0, i1;
            asm("rcp.approx.f32 %0, %1;" : "=f"(i0) : "f"(so0 ? det0 : 1.0f));
            asm("rcp.approx.f32 %0, %1;" : "=f"(i1) : "f"(so1 ? det1 : 1.0f));
            u64 INV = f2pk(i0, i1);

            u64 SX = f2mul(NX, INV);
            u64 SY = f2mul(NY, INV);
            u64 SZ = f2mul(NZ, INV);
            u64 TT = f2fma(GS, SZ, f2fma(GY, SY, f2mul(GX, SX)));

            float sx0, sx1, sy0, sy1, sz0, sz1, tt0, tt1;
            F2UNPK(sx0, sx1, SX);
            F2UNPK(sy0, sy1, SY);
            F2UNPK(sz0, sz1, SZ);
            F2UNPK(tt0, tt1, TT);

            // scalar tails for the two voxels of this pair
            {
                const int j = jp * 2;
                const float x0 = v[1][sm][c0];
                const bool valid = nmsq[j] && so0;
                const float amax = fmaxf(fmaxf(fabsf(sx0), fabsf(sy0)), fabsf(sz0));
                const bool keep = valid && (amax <= 0.7f);
                oc0[j] = (float)d + (keep ? -sz0 : 0.0f);
                oc1[j] = (float)(w0 + j) + (keep ? -sx0 : 0.0f);
                oc2[j] = (float)h + (keep ? -sy0 : 0.0f);
                float ym = valid ? (x0 + 10.0f) : x0;
                if (keep) ym = fmaf(-0.5f, tt0, ym);
                oyv[j] = ym;
            }
            {
                const int j = jp * 2 + 1;
                const float x0 = v[1][sm][c0 + 1];
                const bool valid = nmsq[j] && so1;
                const float amax = fmaxf(fmaxf(fabsf(sx1), fabsf(sy1)), fabsf(sz1));
                const bool keep = valid && (amax <= 0.7f);
                oc0[j] = (float)d + (keep ? -sz1 : 0.0f);
                oc1[j] = (float)(w0 + j) + (keep ? -sx1 : 0.0f);
                oc2[j] = (float)h + (keep ? -sy1 : 0.0f);
                float ym = valid ? (x0 + 10.0f) : x0;
                if (keep) ym = fmaf(-0.5f, tt1, ym);
                oyv[j] = ym;
            }
        }

        *reinterpret_cast<float4*>(o0 + (size_t)r * WW) = make_float4(oc0[0], oc0[1], oc0[2], oc0[3]);
        *reinterpret_cast<float4*>(o1 + (size_t)r * WW) = make_float4(oc1[0], oc1[1], oc1[2], oc1[3]);
        *reinterpret_cast<float4*>(o2 + (size_t)r * WW) = make_float4(oc2[0], oc2[1], oc2[2], oc2[3]);
        *reinterpret_cast<float4*>(oy + (size_t)r * WW) = make_float4(oyv[0], oyv[1], oyv[2], oyv[3]);
    }
}

extern "C" void kernel_launch(void* const* d_in, const int* in_sizes, int n_in,
                              void* d_out, int out_size) {
    const float* x = (const float*)d_in[0];
    float* out = (float*)d_out;
    dim3 grid(BB * DD * (HH / RR));
    dim3 block(192);
    cqi3d_kernel<<<grid, block>>>(x, out);
}

// round 7
// speedup vs baseline: 1.4068x; 1.3168x over previous
#include <cuda_runtime.h>

#define BB 4
#define DD 4
#define HH 768
#define WW 768
#define RR 4

// Load one padded row segment of 6 values: [w0-1, w0..w0+3, w0+4].
__device__ __forceinline__ void load_row6(const float* __restrict__ row, int w0, int lane,
                                          float v[6]) {
    float4 c4 = *reinterpret_cast<const float4*>(row + w0);
    float lv = __shfl_up_sync(0xffffffffu, c4.w, 1);
    float rv = __shfl_down_sync(0xffffffffu, c4.x, 1);
    if (lane == 0) {
        const int wl = (w0 == 0) ? 0 : (w0 - 1);
        lv = __ldg(row + wl);
    }
    if (lane == 31) {
        const int wr = (w0 + 4 >= WW) ? (WW - 1) : (w0 + 4);
        rv = __ldg(row + wr);
    }
    v[0] = lv; v[1] = c4.x; v[2] = c4.y; v[3] = c4.z; v[4] = c4.w; v[5] = rv;
}

__global__ __launch_bounds__(192)
void cqi3d_kernel(const float* __restrict__ x, float* __restrict__ out) {
    const int tid  = threadIdx.x;
    const int lane = tid & 31;
    const int w0   = tid * 4;
    const int hb   = (blockIdx.x % (HH / RR)) * RR;
    const int p    = blockIdx.x / (HH / RR);
    const int d    = p % DD;
    const int b    = p / DD;

    const int dm = (d == 0) ? 0 : d - 1;
    const int dp = (d == DD - 1) ? (DD - 1) : d + 1;
    const float* pl0 = x + ((size_t)(b * DD + dm) * HH) * WW;
    const float* pl1 = x + ((size_t)(b * DD + d ) * HH) * WW;
    const float* pl2 = x + ((size_t)(b * DD + dp) * HH) * WW;

    float v[3][3][6];   // [plane][slot][k]
    float rm9[3][6];    // per-slot 3-plane column max

    {
        const int ht = (hb == 0) ? 0 : (hb - 1);
        load_row6(pl0 + (size_t)ht * WW, w0, lane, v[0][0]);
        load_row6(pl1 + (size_t)ht * WW, w0, lane, v[1][0]);
        load_row6(pl2 + (size_t)ht * WW, w0, lane, v[2][0]);
        load_row6(pl0 + (size_t)hb * WW, w0, lane, v[0][1]);
        load_row6(pl1 + (size_t)hb * WW, w0, lane, v[1][1]);
        load_row6(pl2 + (size_t)hb * WW, w0, lane, v[2][1]);
        #pragma unroll
        for (int k = 0; k < 6; k++) {
            rm9[0][k] = fmaxf(fmaxf(v[0][0][k], v[1][0][k]), v[2][0][k]);
            rm9[1][k] = fmaxf(fmaxf(v[0][1][k], v[1][1][k]), v[2][1][k]);
        }
    }

    const size_t HW = (size_t)HH * WW;
    const size_t sp = (size_t)hb * WW + w0;
    float* o0 = out + ((size_t)(b * 3 + 0) * DD + d) * HW + sp;
    float* o1 = out + ((size_t)(b * 3 + 1) * DD + d) * HW + sp;
    float* o2 = out + ((size_t)(b * 3 + 2) * DD + d) * HW + sp;
    float* oy = out + (size_t)3 * BB * DD * HW + ((size_t)(b * DD + d)) * HW + sp;

    #pragma unroll
    for (int r = 0; r < RR; r++) {
        const int st = r % 3;
        const int sm = (r + 1) % 3;
        const int sb = (r + 2) % 3;
        const int h  = hb + r;

        {
            const int hn = (h + 1 >= HH) ? (HH - 1) : (h + 1);
            load_row6(pl0 + (size_t)hn * WW, w0, lane, v[0][sb]);
            load_row6(pl1 + (size_t)hn * WW, w0, lane, v[1][sb]);
            load_row6(pl2 + (size_t)hn * WW, w0, lane, v[2][sb]);
            #pragma unroll
            for (int k = 0; k < 6; k++)
                rm9[sb][k] = fmaxf(fmaxf(v[0][sb][k], v[1][sb][k]), v[2][sb][k]);
        }

        // ---- NMS (separable): vm = vertical max of top/bottom slot maxima ----
        float vm[6];
        #pragma unroll
        for (int k = 0; k < 6; k++) vm[k] = fmaxf(rm9[st][k], rm9[sb][k]);

        bool nmsq[4];
        unsigned bal[4];
        #pragma unroll
        for (int j = 0; j < 4; j++) {
            const int c = j + 1;
            float nb = fmaxf(vm[c - 1], vm[c]);
            nb = fmaxf(nb, vm[c + 1]);
            nb = fmaxf(nb, rm9[sm][c - 1]);
            nb = fmaxf(nb, rm9[sm][c + 1]);
            nb = fmaxf(nb, fmaxf(v[0][sm][c], v[2][sm][c]));
            nb = fmaxf(nb, 0.0f);
            nmsq[j] = (v[1][sm][c] > nb);
            bal[j] = __ballot_sync(0xffffffffu, nmsq[j]);
        }

        // ---- shared row differences (CSE for gy/dxy and gs/dys/dxs) ----
        float diffbt[6], d20sm[6];
        #pragma unroll
        for (int k = 0; k < 6; k++) {
            diffbt[k] = v[1][sb][k] - v[1][st][k];
            d20sm[k]  = v[2][sm][k] - v[0][sm][k];
        }

        float oc0[4], oc1[4], oc2[4], oyv[4];
        const float fh = (float)h;

        #pragma unroll
        for (int j = 0; j < 4; j++) {
            const int c = j + 1;
            const float x0 = v[1][sm][c];

            if (bal[j]) {   // warp-uniform: at least one lane is a strict maximum
                const float gx = 0.5f * (v[1][sm][c + 1] - v[1][sm][c - 1]);
                const float gy = 0.5f * diffbt[c];
                const float gs = 0.5f * d20sm[c];

                const float dxx = v[1][sm][c + 1] + v[1][sm][c - 1] - 2.0f * x0;
                const float dyy = v[1][sb][c]     + v[1][st][c]     - 2.0f * x0;
                const float dss = v[2][sm][c]     + v[0][sm][c]     - 2.0f * x0;

                const float dxy =  0.25f * (diffbt[c + 1] - diffbt[c - 1]);
                const float dys = -0.25f * ((v[2][sb][c] - v[0][sb][c]) - (v[2][st][c] - v[0][st][c]));
                const float dxs = -0.25f * (d20sm[c + 1] - d20sm[c - 1]);

                const float cf00 = dyy * dss - dys * dys;
                const float cf01 = dxy * dss - dys * dxs;
                const float cf02 = dxy * dys - dyy * dxs;
                const float det  = dxx * cf00 - dxy * cf01 + dxs * cf02;
                const bool solved = (det != 0.0f);
                float inv;
                asm("rcp.approx.f32 %0, %1;" : "=f"(inv) : "f"(solved ? det : 1.0f));

                const float t0 = gy * dss - dys * gs;
                const float t1 = gy * dys - dyy * gs;
                const float t2 = dxy * gs - gy * dxs;

                const float sx = (gx  * cf00 - dxy * t0   + dxs * t1) * inv;
                const float sy = (dxx * t0   - gx  * cf01 + dxs * t2) * inv;
                const float ss = (-dxx * t1  - dxy * t2   + gx  * cf02) * inv;

                const bool valid = nmsq[j] && solved;
                const float amax = fmaxf(fmaxf(fabsf(sx), fabsf(sy)), fabsf(ss));
                const bool keep = valid && (amax <= 0.7f);

                oc0[j] = (float)d + (keep ? -ss : 0.0f);
                oc1[j] = (float)(w0 + j) + (keep ? -sx : 0.0f);
                oc2[j] = fh + (keep ? -sy : 0.0f);

                float ym = valid ? (x0 + 10.0f) : x0;
                if (keep) {
                    const float t = fmaf(gx, sx, fmaf(gy, sy, gs * ss));
                    ym = fmaf(-0.5f, t, ym);
                }
                oyv[j] = ym;
            } else {        // no maximum anywhere in this warp column: trivial output
                oc0[j] = (float)d;
                oc1[j] = (float)(w0 + j);
                oc2[j] = fh;
                oyv[j] = x0;
            }
        }

        *reinterpret_cast<float4*>(o0 + (size_t)r * WW) = make_float4(oc0[0], oc0[1], oc0[2], oc0[3]);
        *reinterpret_cast<float4*>(o1 + (size_t)r * WW) = make_float4(oc1[0], oc1[1], oc1[2], oc1[3]);
        *reinterpret_cast<float4*>(o2 + (size_t)r * WW) = make_float4(oc2[0], oc2[1], oc2[2], oc2[3]);
        *reinterpret_cast<float4*>(oy + (size_t)r * WW) = make_float4(oyv[0], oyv[1], oyv[2], oyv[3]);
    }
}

extern "C" void kernel_launch(void* const* d_in, const int* in_sizes, int n_in,
                              void* d_out, int out_size) {
    const float* x = (const float*)d_in[0];
    float* out = (float*)d_out;
    dim3 grid(BB * DD * (HH / RR));
    dim3 block(192);
    cqi3d_kernel<<<grid, block>>>(x, out);
}

// round 8
// speedup vs baseline: 1.4260x; 1.0136x over previous
#include <cuda_runtime.h>

#define BB 4
#define DD 4
#define HH 768
#define WW 768
#define RR 4

// Load one padded row segment of 6 values: [w0-1, w0..w0+3, w0+4].
__device__ __forceinline__ void load_row6(const float* __restrict__ row, int w0, int lane,
                                          float v[6]) {
    float4 c4 = *reinterpret_cast<const float4*>(row + w0);
    float lv = __shfl_up_sync(0xffffffffu, c4.w, 1);
    float rv = __shfl_down_sync(0xffffffffu, c4.x, 1);
    if (lane == 0) {
        const int wl = (w0 == 0) ? 0 : (w0 - 1);
        lv = __ldg(row + wl);
    }
    if (lane == 31) {
        const int wr = (w0 + 4 >= WW) ? (WW - 1) : (w0 + 4);
        rv = __ldg(row + wr);
    }
    v[0] = lv; v[1] = c4.x; v[2] = c4.y; v[3] = c4.z; v[4] = c4.w; v[5] = rv;
}

__global__ __launch_bounds__(192, 4)
void cqi3d_kernel(const float* __restrict__ x, float* __restrict__ out) {
    const int tid  = threadIdx.x;
    const int lane = tid & 31;
    const int w0   = tid * 4;
    const int hb   = (blockIdx.x % (HH / RR)) * RR;
    const int p    = blockIdx.x / (HH / RR);
    const int d    = p % DD;
    const int b    = p / DD;

    const int dm = (d == 0) ? 0 : d - 1;
    const int dp = (d == DD - 1) ? (DD - 1) : d + 1;
    const float* pl0 = x + ((size_t)(b * DD + dm) * HH) * WW;
    const float* pl1 = x + ((size_t)(b * DD + d ) * HH) * WW;
    const float* pl2 = x + ((size_t)(b * DD + dp) * HH) * WW;

    float v[3][3][6];   // [plane][slot][k]
    float rm9[3][6];    // per-slot 3-plane column max

    {
        const int ht = (hb == 0) ? 0 : (hb - 1);
        load_row6(pl0 + (size_t)ht * WW, w0, lane, v[0][0]);
        load_row6(pl1 + (size_t)ht * WW, w0, lane, v[1][0]);
        load_row6(pl2 + (size_t)ht * WW, w0, lane, v[2][0]);
        load_row6(pl0 + (size_t)hb * WW, w0, lane, v[0][1]);
        load_row6(pl1 + (size_t)hb * WW, w0, lane, v[1][1]);
        load_row6(pl2 + (size_t)hb * WW, w0, lane, v[2][1]);
        #pragma unroll
        for (int k = 0; k < 6; k++) {
            rm9[0][k] = fmaxf(fmaxf(v[0][0][k], v[1][0][k]), v[2][0][k]);
            rm9[1][k] = fmaxf(fmaxf(v[0][1][k], v[1][1][k]), v[2][1][k]);
        }
    }

    const size_t HW = (size_t)HH * WW;
    const size_t sp = (size_t)hb * WW + w0;
    float* o0 = out + ((size_t)(b * 3 + 0) * DD + d) * HW + sp;
    float* o1 = out + ((size_t)(b * 3 + 1) * DD + d) * HW + sp;
    float* o2 = out + ((size_t)(b * 3 + 2) * DD + d) * HW + sp;
    float* oy = out + (size_t)3 * BB * DD * HW + ((size_t)(b * DD + d)) * HW + sp;

    #pragma unroll
    for (int r = 0; r < RR; r++) {
        const int st = r % 3;
        const int sm = (r + 1) % 3;
        const int sb = (r + 2) % 3;
        const int h  = hb + r;

        {
            const int hn = (h + 1 >= HH) ? (HH - 1) : (h + 1);
            load_row6(pl0 + (size_t)hn * WW, w0, lane, v[0][sb]);
            load_row6(pl1 + (size_t)hn * WW, w0, lane, v[1][sb]);
            load_row6(pl2 + (size_t)hn * WW, w0, lane, v[2][sb]);
            #pragma unroll
            for (int k = 0; k < 6; k++)
                rm9[sb][k] = fmaxf(fmaxf(v[0][sb][k], v[1][sb][k]), v[2][sb][k]);
        }

        // ---- NMS (separable): vm = vertical max of top/bottom slot maxima ----
        float vm[6];
        #pragma unroll
        for (int k = 0; k < 6; k++) vm[k] = fmaxf(rm9[st][k], rm9[sb][k]);

        bool nmsq[4];
        unsigned bal[4];
        #pragma unroll
        for (int j = 0; j < 4; j++) {
            const int c = j + 1;
            float nb = fmaxf(vm[c - 1], vm[c]);
            nb = fmaxf(nb, vm[c + 1]);
            nb = fmaxf(nb, rm9[sm][c - 1]);
            nb = fmaxf(nb, rm9[sm][c + 1]);
            nb = fmaxf(nb, fmaxf(v[0][sm][c], v[2][sm][c]));
            nb = fmaxf(nb, 0.0f);
            nmsq[j] = (v[1][sm][c] > nb);
            bal[j] = __ballot_sync(0xffffffffu, nmsq[j]);
        }

        // ---- shared row differences (CSE for gy/dxy and gs/dys/dxs) ----
        float diffbt[6], d20sm[6];
        #pragma unroll
        for (int k = 0; k < 6; k++) {
            diffbt[k] = v[1][sb][k] - v[1][st][k];
            d20sm[k]  = v[2][sm][k] - v[0][sm][k];
        }

        float oc0[4], oc1[4], oc2[4], oyv[4];
        const float fh = (float)h;

        #pragma unroll
        for (int j = 0; j < 4; j++) {
            const int c = j + 1;
            const float x0 = v[1][sm][c];

            if (bal[j]) {   // warp-uniform: at least one lane is a strict maximum
                const float gx = 0.5f * (v[1][sm][c + 1] - v[1][sm][c - 1]);
                const float gy = 0.5f * diffbt[c];
                const float gs = 0.5f * d20sm[c];

                const float dxx = v[1][sm][c + 1] + v[1][sm][c - 1] - 2.0f * x0;
                const float dyy = v[1][sb][c]     + v[1][st][c]     - 2.0f * x0;
                const float dss = v[2][sm][c]     + v[0][sm][c]     - 2.0f * x0;

                const float dxy =  0.25f * (diffbt[c + 1] - diffbt[c - 1]);
                const float dys = -0.25f * ((v[2][sb][c] - v[0][sb][c]) - (v[2][st][c] - v[0][st][c]));
                const float dxs = -0.25f * (d20sm[c + 1] - d20sm[c - 1]);

                const float cf00 = dyy * dss - dys * dys;
                const float cf01 = dxy * dss - dys * dxs;
                const float cf02 = dxy * dys - dyy * dxs;
                const float det  = dxx * cf00 - dxy * cf01 + dxs * cf02;
                const bool solved = (det != 0.0f);
                float inv;
                asm("rcp.approx.f32 %0, %1;" : "=f"(inv) : "f"(solved ? det : 1.0f));

                const float t0 = gy * dss - dys * gs;
                const float t1 = gy * dys - dyy * gs;
                const float t2 = dxy * gs - gy * dxs;

                const float sx = (gx  * cf00 - dxy * t0   + dxs * t1) * inv;
                const float sy = (dxx * t0   - gx  * cf01 + dxs * t2) * inv;
                const float ss = (-dxx * t1  - dxy * t2   + gx  * cf02) * inv;

                const bool valid = nmsq[j] && solved;
                const float amax = fmaxf(fmaxf(fabsf(sx), fabsf(sy)), fabsf(ss));
                const bool keep = valid && (amax <= 0.7f);

                oc0[j] = (float)d + (keep ? -ss : 0.0f);
                oc1[j] = (float)(w0 + j) + (keep ? -sx : 0.0f);
                oc2[j] = fh + (keep ? -sy : 0.0f);

                float ym = valid ? (x0 + 10.0f) : x0;
                if (keep) {
                    const float t = fmaf(gx, sx, fmaf(gy, sy, gs * ss));
                    ym = fmaf(-0.5f, t, ym);
                }
                oyv[j] = ym;
            } else {        // no maximum anywhere in this warp column: trivial output
                oc0[j] = (float)d;
                oc1[j] = (float)(w0 + j);
                oc2[j] = fh;
                oyv[j] = x0;
            }
        }

        *reinterpret_cast<float4*>(o0 + (size_t)r * WW) = make_float4(oc0[0], oc0[1], oc0[2], oc0[3]);
        *reinterpret_cast<float4*>(o1 + (size_t)r * WW) = make_float4(oc1[0], oc1[1], oc1[2], oc1[3]);
        *reinterpret_cast<float4*>(o2 + (size_t)r * WW) = make_float4(oc2[0], oc2[1], oc2[2], oc2[3]);
        *reinterpret_cast<float4*>(oy + (size_t)r * WW) = make_float4(oyv[0], oyv[1], oyv[2], oyv[3]);
    }
}

extern "C" void kernel_launch(void* const* d_in, const int* in_sizes, int n_in,
                              void* d_out, int out_size) {
    const float* x = (const float*)d_in[0];
    float* out = (float*)d_out;
    dim3 grid(BB * DD * (HH / RR));
    dim3 block(192);
    cqi3d_kernel<<<grid, block>>>(x, out);
}